// round 15
// baseline (speedup 1.0000x reference)
#include <cuda_runtime.h>
#include <math.h>
#include <stdint.h>

typedef unsigned long long ull;

#define T_STEPS 1024
#define BATCH   64
#define IN_DIM  512
#define H_DIM   1024

#define NCTA         128
#define SCAN_THREADS 512
#define NWARPS       16
#define COLS_PER_CTA 8          // 128 CTAs * 8 cols = 1024
#define KPW          64         // k per warp (16 warps * 64 = 1024)
#define SUBK         16         // k per staged subslice (R9 double-buffer)
#define NSUB         (KPW / SUBK)       // 4 subslices
#define WPK_PITCH    1030       // ull pitch per column (bank-stagger)
#define FLAG_STRIDE  16         // ull stride between CTA flags (128B lines)

// Transposed hidden state, double-buffered: g_ht[p][col*BATCH + row]
__device__ float g_ht[2][H_DIM * BATCH];
// Prologue grid barrier: monotonic counter + epoch word
__device__ ull g_count = 0ULL;
__device__ ull g_epoch = 0ULL;
// Per-CTA progress flags (monotonic across graph replays)
__device__ ull g_flags[NCTA * FLAG_STRIDE];

// ---------------------------------------------------------------------------
// packed f32x2 helpers (Blackwell sm_103a)
// ---------------------------------------------------------------------------
__device__ __forceinline__ ull pack2(float a, float b)
{
    ull r; asm("mov.b64 %0, {%1, %2};" : "=l"(r) : "f"(a), "f"(b)); return r;
}
__device__ __forceinline__ void unpack2(ull v, float& a, float& b)
{
    asm("mov.b64 {%0, %1}, %2;" : "=f"(a), "=f"(b) : "l"(v));
}
__device__ __forceinline__ void fma2(ull& acc, ull a, ull b)
{
    asm("fma.rn.f32x2 %0, %1, %2, %0;" : "+l"(acc) : "l"(a), "l"(b));
}
__device__ __forceinline__ ull add2(ull a, ull b)
{
    ull r; asm("add.rn.f32x2 %0, %1, %2;" : "=l"(r) : "l"(a), "l"(b)); return r;
}

// ---------------------------------------------------------------------------
// Kernel 1: xproj = x @ Wx + b  (out doubles as xproj buffer) — R6 version
// ---------------------------------------------------------------------------
__global__ void __launch_bounds__(256) xproj_kernel(
    const float* __restrict__ x,
    const float* __restrict__ W,     // full (IN+H, H); Wx = rows [0,512)
    const float* __restrict__ bias,
    float* __restrict__ out)
{
    __shared__ float As[16][64];     // [k][m]
    __shared__ float Bs[16][64];     // [k][n]

    const int tid  = threadIdx.x;
    const int row0 = blockIdx.y * 64;
    const int col0 = blockIdx.x * 64;

    const int ty = tid >> 4;               // 0..15
    const int tx = tid & 15;               // 0..15

    const int lmA = tid >> 2;              // 0..63
    const int lkA = (tid & 3) << 2;        // 0,4,8,12
    const int lkB = tid >> 4;              // 0..15
    const int lnB = (tid & 15) << 2;       // 0..60

    ull acc01[4], acc23[4];
#pragma unroll
    for (int i = 0; i < 4; ++i) { acc01[i] = 0ULL; acc23[i] = 0ULL; }

    const float* xg = x + (size_t)(row0 + lmA) * IN_DIM + lkA;

    for (int k0 = 0; k0 < IN_DIM; k0 += 16) {
        float4 av = *(const float4*)(xg + k0);
        As[lkA + 0][lmA] = av.x;
        As[lkA + 1][lmA] = av.y;
        As[lkA + 2][lmA] = av.z;
        As[lkA + 3][lmA] = av.w;

        float4 bv = *(const float4*)(W + (size_t)(k0 + lkB) * H_DIM + col0 + lnB);
        *(float4*)&Bs[lkB][lnB] = bv;

        __syncthreads();
#pragma unroll
        for (int k = 0; k < 16; ++k) {
            float4 a = *(const float4*)&As[k][ty << 2];
            ulonglong2 b = *(const ulonglong2*)&Bs[k][tx << 2];
            ull ax = pack2(a.x, a.x);
            ull ay = pack2(a.y, a.y);
            ull az = pack2(a.z, a.z);
            ull aw = pack2(a.w, a.w);
            fma2(acc01[0], ax, b.x); fma2(acc23[0], ax, b.y);
            fma2(acc01[1], ay, b.x); fma2(acc23[1], ay, b.y);
            fma2(acc01[2], az, b.x); fma2(acc23[2], az, b.y);
            fma2(acc01[3], aw, b.x); fma2(acc23[3], aw, b.y);
        }
        __syncthreads();
    }

    float4 bb = *(const float4*)(bias + col0 + (tx << 2));
#pragma unroll
    for (int i = 0; i < 4; ++i) {
        float s0, s1, s2, s3;
        unpack2(acc01[i], s0, s1);
        unpack2(acc23[i], s2, s3);
        float4 o;
        o.x = s0 + bb.x;
        o.y = s1 + bb.y;
        o.z = s2 + bb.z;
        o.w = s3 + bb.w;
        *(float4*)(out + (size_t)(row0 + (ty << 2) + i) * H_DIM + col0 + (tx << 2)) = o;
    }
}

// ---------------------------------------------------------------------------
// Scan kernel helpers
// ---------------------------------------------------------------------------
__device__ __forceinline__ void cp_async16(float* sdst, const float* gsrc)
{
    unsigned sa = (unsigned)__cvta_generic_to_shared(sdst);
    asm volatile("cp.async.cg.shared.global [%0], [%1], 16;\n" :: "r"(sa), "l"(gsrc));
}

// warp-private subslice staging: SUBK*BATCH = 1024 floats = 256 float4
__device__ __forceinline__ void stage_sub(const float* gsrc, float* sdst, int lane)
{
#pragma unroll
    for (int i = 0; i < 8; ++i) {
        int idx = lane + i * 32;
        cp_async16(sdst + idx * 4, gsrc + idx * 4);
    }
}

// Prologue-only grid barrier (counter + epoch)
__device__ __forceinline__ void grid_barrier()
{
    __syncthreads();
    if (threadIdx.x == 0) {
        __threadfence();
        ull old = atomicAdd(&g_count, 1ULL);
        ull target = (old / NCTA + 1ULL) * (ull)NCTA;
        if (old + 1ULL == target) {
            asm volatile("st.release.gpu.global.u64 [%0], %1;" :: "l"(&g_epoch), "l"(target));
        } else {
            ull cur;
            do {
                asm volatile("ld.acquire.gpu.global.u64 %0, [%1];" : "=l"(cur) : "l"(&g_epoch));
            } while (cur < target);
        }
    }
    __syncthreads();
}

// Parallel producer wait: lanes 0..7 each acquire-poll one producer flag.
// Warp w's k-range is produced by CTAs w*8..w*8+7 exactly.
__device__ __forceinline__ void wait_producers(int wid, int lane, ull target)
{
    if (lane < 8) {
        const ull* f = &g_flags[(wid * 8 + lane) * FLAG_STRIDE];
        ull cur;
        do {
            asm volatile("ld.acquire.gpu.global.u64 %0, [%1];" : "=l"(cur) : "l"(f));
        } while (cur < target);
    }
    __syncwarp();
}

// ---------------------------------------------------------------------------
// Kernel 2: persistent recurrent scan — R9 staging + DISTRIBUTED FLAG SYNC.
// No per-step global barrier: each CTA release-publishes its progress flag;
// each warp acquire-waits only on its 8 producer CTAs. Epilogue split around
// a second __syncthreads so the red buffer is reusable while the tail
// (tanh/stores/flag) overlaps with other warps' next-step compute.
// ---------------------------------------------------------------------------
__global__ void __launch_bounds__(SCAN_THREADS) scan_kernel(
    const float* __restrict__ hinit,  // initial h (B,H)
    const float* __restrict__ W,      // Wh = rows [512, 1536)
    float* __restrict__ out)
{
    extern __shared__ float smem[];
    ull*   wpk  = (ull*)smem;                            // 8 x 1030 ull = 65920 B
    float* hball = smem + 2 * 8 * WPK_PITCH;             // 16 x 2 x 1024 f = 128 KB
    ulonglong2* red = (ulonglong2*)(hball + NWARPS * 2 * SUBK * BATCH);  // 32 KB

    const int tid  = threadIdx.x;
    const int wid  = tid >> 5;                // warp 0..15
    const int lane = tid & 31;
    const int rg   = lane & 15;               // rows rg*4..rg*4+3
    const int cg   = lane >> 4;               // cols cg*4..cg*4+3
    const int col0 = blockIdx.x * COLS_PER_CTA;
    const int c0   = cg * 4;
    const int r0   = rg * 4;

    float* myb = hball + wid * (2 * SUBK * BATCH);   // my double buffer

    // Base epoch for this launch (own flag; only this CTA ever writes it)
    ull base;
    asm volatile("ld.global.u64 %0, [%1];" : "=l"(base)
                 : "l"(&g_flags[blockIdx.x * FLAG_STRIDE]));

    // Prologue A: transpose my 8 columns of initial h into g_ht[0]
    {
        int cc = tid >> 6;        // 0..7
        int r  = tid & 63;        // 0..63
        g_ht[0][(col0 + cc) * BATCH + r] = hinit[(size_t)r * H_DIM + col0 + cc];
    }

    // Prologue B: pre-pack resident Wh slice: wpk[cc][k] = (w, w)
    for (int i = tid; i < H_DIM * COLS_PER_CTA; i += SCAN_THREADS) {
        int cc = i >> 10;
        int k  = i & 1023;
        float w = W[(size_t)(IN_DIM + k) * H_DIM + col0 + cc];
        wpk[cc * WPK_PITCH + k] = pack2(w, w);
    }

    grid_barrier();   // all transposes visible before step-0 staging

    // per-thread weight row pointers (4 cols), absolute-k indexed
    const ull* wp0 = wpk + (c0 + 0) * WPK_PITCH;
    const ull* wp1 = wpk + (c0 + 1) * WPK_PITCH;
    const ull* wp2 = wpk + (c0 + 2) * WPK_PITCH;
    const ull* wp3 = wpk + (c0 + 3) * WPK_PITCH;

    const int kb0 = wid * KPW;

    // epilogue thread's output column and row offsets (warps 0..3 only)
    const int  colE = col0 + c0 + wid;                  // valid when wid<4
    const size_t eo0 = (size_t)(r0 + 0) * H_DIM + colE;
    const size_t eo1 = (size_t)(r0 + 1) * H_DIM + colE;
    const size_t eo2 = (size_t)(r0 + 2) * H_DIM + colE;
    const size_t eo3 = (size_t)(r0 + 3) * H_DIM + colE;

    // prefetch xp for step 0 (epilogue warps)
    float xp0 = 0.f, xp1 = 0.f, xp2 = 0.f, xp3 = 0.f;
    if (wid < 4) {
        xp0 = out[eo0]; xp1 = out[eo1]; xp2 = out[eo2]; xp3 = out[eo3];
    }

    for (int t = 0; t < T_STEPS; ++t) {
        const float* gh  = g_ht[t & 1];
        float*       ghn = g_ht[(t + 1) & 1];
        float*       outt = out + (size_t)t * BATCH * H_DIM;

        // wait for my 8 producer CTAs to finish step t-1 (parallel polls)
        wait_producers(wid, lane, base + (ull)t);

        ull acc[2][4];
#pragma unroll
        for (int j = 0; j < 4; ++j) { acc[0][j] = 0ULL; acc[1][j] = 0ULL; }

        // stage my subslice 0
        stage_sub(gh + (size_t)kb0 * BATCH, myb, lane);
        asm volatile("cp.async.commit_group;\n" ::: "memory");

#pragma unroll
        for (int s = 0; s < NSUB; ++s) {
            if (s + 1 < NSUB) {
                stage_sub(gh + (size_t)(kb0 + (s + 1) * SUBK) * BATCH,
                          myb + ((s + 1) & 1) * (SUBK * BATCH), lane);
                asm volatile("cp.async.commit_group;\n" ::: "memory");
                asm volatile("cp.async.wait_group 1;\n" ::: "memory");
            } else {
                asm volatile("cp.async.wait_group 0;\n" ::: "memory");
            }
            __syncwarp();

            const float* hb = myb + (s & 1) * (SUBK * BATCH) + r0;
            const int kw = kb0 + s * SUBK;
#pragma unroll
            for (int kk = 0; kk < SUBK; kk += 2) {
                const float* hp = hb + kk * BATCH;
                ulonglong2 hA = *(const ulonglong2*)(hp);          // rows r0..r0+3, k
                ulonglong2 hB = *(const ulonglong2*)(hp + BATCH);  // k+1
                ulonglong2 w0 = *(const ulonglong2*)(wp0 + kw + kk);
                ulonglong2 w1 = *(const ulonglong2*)(wp1 + kw + kk);
                ulonglong2 w2 = *(const ulonglong2*)(wp2 + kw + kk);
                ulonglong2 w3 = *(const ulonglong2*)(wp3 + kw + kk);
                fma2(acc[0][0], hA.x, w0.x); fma2(acc[1][0], hA.y, w0.x);
                fma2(acc[0][1], hA.x, w1.x); fma2(acc[1][1], hA.y, w1.x);
                fma2(acc[0][2], hA.x, w2.x); fma2(acc[1][2], hA.y, w2.x);
                fma2(acc[0][3], hA.x, w3.x); fma2(acc[1][3], hA.y, w3.x);
                fma2(acc[0][0], hB.x, w0.y); fma2(acc[1][0], hB.y, w0.y);
                fma2(acc[0][1], hB.x, w1.y); fma2(acc[1][1], hB.y, w1.y);
                fma2(acc[0][2], hB.x, w2.y); fma2(acc[1][2], hB.y, w2.y);
                fma2(acc[0][3], hB.x, w3.y); fma2(acc[1][3], hB.y, w3.y);
            }
            __syncwarp();   // all lanes done reading before buffer is re-staged
        }

        // store partials: red[j][s=wid][lane], lane-contiguous
#pragma unroll
        for (int j = 0; j < 4; ++j)
            red[(j * NWARPS + wid) * 32 + lane] = make_ulonglong2(acc[0][j], acc[1][j]);
        __syncthreads();   // sync A: all partials stored

        // reduction reads (epilogue warps only) — must finish before red reuse
        ull s01 = 0ULL, s23 = 0ULL;
        if (wid < 4) {
#pragma unroll
            for (int s = 0; s < NWARPS; ++s) {
                ulonglong2 p = red[(wid * NWARPS + s) * 32 + lane];
                s01 = add2(s01, p.x);
                s23 = add2(s23, p.y);
            }
        }
        __syncthreads();   // sync B: red free; warps 4..15 proceed to step t+1

        if (wid < 4) {
            float v0, v1, v2, v3;
            unpack2(s01, v0, v1);
            unpack2(s23, v2, v3);
            v0 = tanhf(v0 + xp0);
            v1 = tanhf(v1 + xp1);
            v2 = tanhf(v2 + xp2);
            v3 = tanhf(v3 + xp3);

            // hidden state to output history (column-scattered, small)
            outt[eo0] = v0;
            outt[eo1] = v1;
            outt[eo2] = v2;
            outt[eo3] = v3;

            // transposed copy for next step's staging (coalesced float4)
            *(float4*)&ghn[colE * BATCH + r0] = make_float4(v0, v1, v2, v3);

            // prefetch next step's xp (overlaps with other warps' compute)
            if (t + 1 < T_STEPS) {
                const float* outn = outt + BATCH * H_DIM;
                xp0 = outn[eo0]; xp1 = outn[eo1]; xp2 = outn[eo2]; xp3 = outn[eo3];
            }

            // all 4 epilogue warps done -> publish progress flag
            asm volatile("bar.sync 1, 128;" ::: "memory");
            if (tid == 0) {
                __threadfence();
                asm volatile("st.release.gpu.global.u64 [%0], %1;"
                             :: "l"(&g_flags[blockIdx.x * FLAG_STRIDE]),
                                "l"(base + (ull)(t + 1)));
            }
        }
    }
}

// ---------------------------------------------------------------------------
extern "C" void kernel_launch(void* const* d_in, const int* in_sizes, int n_in,
                              void* d_out, int out_size)
{
    (void)in_sizes; (void)n_in; (void)out_size;
    const float* x = (const float*)d_in[0];
    const float* h = (const float*)d_in[1];
    const float* W = (const float*)d_in[2];
    const float* b = (const float*)d_in[3];
    float* out = (float*)d_out;

    // 1) xproj = x @ Wx + b  -> out
    dim3 grid_x(H_DIM / 64, (T_STEPS * BATCH) / 64);
    xproj_kernel<<<grid_x, 256>>>(x, W, b, out);

    // 2) persistent recurrent scan
    // smem: weights 65920 + warp buffers 131072 + reduction 32768 = 229760 B
    const size_t smem_bytes = (2 * 8 * WPK_PITCH + NWARPS * 2 * SUBK * BATCH) * sizeof(float)
                            + 4 * NWARPS * 32 * sizeof(ulonglong2);
    static int smem_set = 0;
    if (!smem_set) {
        cudaFuncSetAttribute(scan_kernel, cudaFuncAttributeMaxDynamicSharedMemorySize,
                             (int)smem_bytes);
        smem_set = 1;
    }
    scan_kernel<<<NCTA, SCAN_THREADS, smem_bytes>>>(h, W, out);
}

// round 17
// speedup vs baseline: 1.6061x; 1.6061x over previous
#include <cuda_runtime.h>
#include <math.h>
#include <stdint.h>

typedef unsigned long long ull;

#define T_STEPS 1024
#define BATCH   64
#define IN_DIM  512
#define H_DIM   1024

#define NCTA         128
#define SCAN_THREADS 512
#define NWARPS       16
#define COLS_PER_CTA 8          // 128 CTAs * 8 cols = 1024
#define KPW          64         // k per warp (16 warps * 64 = 1024)
#define SUBK         16         // k per staged subslice (8 k2-pairs)
#define NSUB         (KPW / SUBK)       // 4 subslices, double-buffered
#define RED_PITCH    17         // ull pitch per output slot (bank-stagger)

// Hidden state in K-PAIR GRANULE layout, double-buffered:
// granule(k2, j) = 16B = [h(2j,2k2), h(2j,2k2+1), h(2j+1,2k2), h(2j+1,2k2+1)]
//   -> ulonglong2 .x = row 2j's (even-k, odd-k) pair, .y = row 2j+1's pair
// float offset of granule = (k2*32 + j)*4
__device__ float g_ht2[2][H_DIM * BATCH];
// Grid barrier: monotonic arrival counter + separately-polled epoch word
__device__ ull g_count = 0ULL;
__device__ ull g_epoch = 0ULL;

// ---------------------------------------------------------------------------
// packed f32x2 helpers (Blackwell sm_103a)
// ---------------------------------------------------------------------------
__device__ __forceinline__ ull pack2(float a, float b)
{
    ull r; asm("mov.b64 %0, {%1, %2};" : "=l"(r) : "f"(a), "f"(b)); return r;
}
__device__ __forceinline__ void unpack2(ull v, float& a, float& b)
{
    asm("mov.b64 {%0, %1}, %2;" : "=f"(a), "=f"(b) : "l"(v));
}
__device__ __forceinline__ void fma2(ull& acc, ull a, ull b)
{
    asm("fma.rn.f32x2 %0, %1, %2, %0;" : "+l"(acc) : "l"(a), "l"(b));
}
__device__ __forceinline__ ull add2(ull a, ull b)
{
    ull r; asm("add.rn.f32x2 %0, %1, %2;" : "=l"(r) : "l"(a), "l"(b)); return r;
}

// ---------------------------------------------------------------------------
// Kernel 1: xproj = x @ Wx + b  (out doubles as xproj buffer) — R6 version
// ---------------------------------------------------------------------------
__global__ void __launch_bounds__(256) xproj_kernel(
    const float* __restrict__ x,
    const float* __restrict__ W,     // full (IN+H, H); Wx = rows [0,512)
    const float* __restrict__ bias,
    float* __restrict__ out)
{
    __shared__ float As[16][64];     // [k][m]
    __shared__ float Bs[16][64];     // [k][n]

    const int tid  = threadIdx.x;
    const int row0 = blockIdx.y * 64;
    const int col0 = blockIdx.x * 64;

    const int ty = tid >> 4;               // 0..15
    const int tx = tid & 15;               // 0..15

    const int lmA = tid >> 2;              // 0..63
    const int lkA = (tid & 3) << 2;        // 0,4,8,12
    const int lkB = tid >> 4;              // 0..15
    const int lnB = (tid & 15) << 2;       // 0..60

    ull acc01[4], acc23[4];
#pragma unroll
    for (int i = 0; i < 4; ++i) { acc01[i] = 0ULL; acc23[i] = 0ULL; }

    const float* xg = x + (size_t)(row0 + lmA) * IN_DIM + lkA;

    for (int k0 = 0; k0 < IN_DIM; k0 += 16) {
        float4 av = *(const float4*)(xg + k0);
        As[lkA + 0][lmA] = av.x;
        As[lkA + 1][lmA] = av.y;
        As[lkA + 2][lmA] = av.z;
        As[lkA + 3][lmA] = av.w;

        float4 bv = *(const float4*)(W + (size_t)(k0 + lkB) * H_DIM + col0 + lnB);
        *(float4*)&Bs[lkB][lnB] = bv;

        __syncthreads();
#pragma unroll
        for (int k = 0; k < 16; ++k) {
            float4 a = *(const float4*)&As[k][ty << 2];
            ulonglong2 b = *(const ulonglong2*)&Bs[k][tx << 2];
            ull ax = pack2(a.x, a.x);
            ull ay = pack2(a.y, a.y);
            ull az = pack2(a.z, a.z);
            ull aw = pack2(a.w, a.w);
            fma2(acc01[0], ax, b.x); fma2(acc23[0], ax, b.y);
            fma2(acc01[1], ay, b.x); fma2(acc23[1], ay, b.y);
            fma2(acc01[2], az, b.x); fma2(acc23[2], az, b.y);
            fma2(acc01[3], aw, b.x); fma2(acc23[3], aw, b.y);
        }
        __syncthreads();
    }

    float4 bb = *(const float4*)(bias + col0 + (tx << 2));
#pragma unroll
    for (int i = 0; i < 4; ++i) {
        float s0, s1, s2, s3;
        unpack2(acc01[i], s0, s1);
        unpack2(acc23[i], s2, s3);
        float4 o;
        o.x = s0 + bb.x;
        o.y = s1 + bb.y;
        o.z = s2 + bb.z;
        o.w = s3 + bb.w;
        *(float4*)(out + (size_t)(row0 + (ty << 2) + i) * H_DIM + col0 + (tx << 2)) = o;
    }
}

// ---------------------------------------------------------------------------
// Scan kernel helpers
// ---------------------------------------------------------------------------
__device__ __forceinline__ void cp_async16(float* sdst, const float* gsrc)
{
    unsigned sa = (unsigned)__cvta_generic_to_shared(sdst);
    asm volatile("cp.async.cg.shared.global [%0], [%1], 16;\n" :: "r"(sa), "l"(gsrc));
}

// warp-private subslice staging: 256 granules = 1024 floats (R9-identical)
__device__ __forceinline__ void stage_sub(const float* gsrc, float* sdst, int lane)
{
#pragma unroll
    for (int i = 0; i < 8; ++i) {
        int idx = lane + i * 32;
        cp_async16(sdst + idx * 4, gsrc + idx * 4);
    }
}

// Counter+epoch barrier: RMWs on g_count never contend with the read-polls,
// which target only g_epoch.
__device__ __forceinline__ void grid_barrier()
{
    __syncthreads();
    if (threadIdx.x == 0) {
        __threadfence();
        ull old = atomicAdd(&g_count, 1ULL);
        ull target = (old / NCTA + 1ULL) * (ull)NCTA;
        if (old + 1ULL == target) {
            asm volatile("st.release.gpu.global.u64 [%0], %1;" :: "l"(&g_epoch), "l"(target));
        } else {
            ull cur;
            do {
                asm volatile("ld.acquire.gpu.global.u64 %0, [%1];" : "=l"(cur) : "l"(&g_epoch));
            } while (cur < target);
        }
    }
    __syncthreads();
}

// ---------------------------------------------------------------------------
// Kernel 2: persistent recurrent scan — K-PAIRED operands (no duplication).
// 128 CTAs x 512 threads (16 warps). CTA owns 8 output columns.
// Warp w owns k2 in [w*32, w*32+32), staged via R9's per-warp cp.async
// double buffers. Lane = jp(0..15) + 16*cg(0..1); thread = rows
// {2jp,2jp+1,2jp+32,2jp+33} x cols cg*4..+3; 16 k-split f32x2 accumulators
// (lanes = even-k / odd-k partials, folded once per step).
// Per k2: 2 h-LDS.128 (2wf ea) + 2 w-LDS.128 (1wf ea) + 16 fma2 — 6wf/16fma2
// (was 8), conflict-free, zero pack ALU in the loop.
// Weights stored as k-pair units wk2[k2][c] (32KB, undup).
// ---------------------------------------------------------------------------
__global__ void __launch_bounds__(SCAN_THREADS) scan_kernel(
    const float* __restrict__ hinit,  // initial h (B,H)
    const float* __restrict__ W,      // Wh = rows [512, 1536)
    float* __restrict__ out)
{
    extern __shared__ float smem[];
    ull*   wk2   = (ull*)smem;                           // 512 k2 x 8 c = 32 KB
    float* hball = smem + 8192;                          // 16 x 2048 f = 128 KB
    ull*   red   = (ull*)(hball + NWARPS * 2 * SUBK * BATCH); // 256*17 ull ~ 34 KB

    const int tid  = threadIdx.x;
    const int wid  = tid >> 5;                // warp 0..15
    const int lane = tid & 31;
    const int jp   = lane & 15;               // rowpair 0..15 (rows 2jp,2jp+1; +32)
    const int cg   = lane >> 4;               // col group 0..1
    const int col0 = blockIdx.x * COLS_PER_CTA;
    const int c0   = cg * 4;

    float* myb = hball + wid * (2 * SUBK * BATCH);   // my double buffer (2 x 4KB)

    // Prologue A: initial h into g_ht2[0] granule layout
    // granule pos = (r&1)*2 + (c&1): .x = row-even k-pair, .y = row-odd k-pair
    {
        int c = col0 + (tid >> 6);   // my column
        int r = tid & 63;            // row
        int off = ((c >> 1) * 32 + (r >> 1)) * 4 + (r & 1) * 2 + (c & 1);
        g_ht2[0][off] = hinit[(size_t)r * H_DIM + c];
    }

    // Prologue B: weights as k-pair units: wk2[k2*8+c] = (W[2k2][c], W[2k2+1][c])
    for (int i = tid; i < 512 * COLS_PER_CTA; i += SCAN_THREADS) {
        int cc = i >> 9;          // 0..7
        int k2 = i & 511;         // 0..511
        float wa = W[(size_t)(IN_DIM + 2 * k2) * H_DIM + col0 + cc];
        float wb = W[(size_t)(IN_DIM + 2 * k2 + 1) * H_DIM + col0 + cc];
        wk2[k2 * 8 + cc] = pack2(wa, wb);
    }

    grid_barrier();   // all transposes visible before step-0 staging

    const int kb2 = wid * 32;     // warp's k2 base

    // epilogue mapping (threads 0..255): output slot o = tid
    const int oE    = tid;                         // valid when tid<256
    const int cE    = oE >> 5;                     // 0..7
    const int halfE = (oE >> 4) & 1;
    const int jpE   = oE & 15;
    const int row0E = 2 * jpE + 32 * halfE;
    const int colE  = col0 + cE;
    const size_t eo0 = (size_t)row0E * H_DIM + colE;
    const size_t eo1 = eo0 + H_DIM;
    // granule base for (row0E, colE); row0E even -> my rows at +0*2+(c&1), +1*2+(c&1)
    const int ghn_base = ((colE >> 1) * 32 + (row0E >> 1)) * 4 + (colE & 1);

    // prefetch xp for step 0
    float xp0 = 0.f, xp1 = 0.f;
    if (tid < 256) { xp0 = out[eo0]; xp1 = out[eo1]; }

    for (int t = 0; t < T_STEPS; ++t) {
        const float* gh  = g_ht2[t & 1];
        float*       ghn = g_ht2[(t + 1) & 1];
        float*       outt = out + (size_t)t * BATCH * H_DIM;

        ull acc[4][4];   // [row i][col j], lanes = (even-k partial, odd-k partial)
#pragma unroll
        for (int i = 0; i < 4; ++i)
#pragma unroll
            for (int j = 0; j < 4; ++j) acc[i][j] = 0ULL;

        // stage my subslice 0
        stage_sub(gh + (size_t)kb2 * 128, myb, lane);
        asm volatile("cp.async.commit_group;\n" ::: "memory");

#pragma unroll
        for (int s = 0; s < NSUB; ++s) {
            if (s + 1 < NSUB) {
                stage_sub(gh + (size_t)kb2 * 128 + (size_t)(s + 1) * 1024,
                          myb + ((s + 1) & 1) * (SUBK * BATCH), lane);
                asm volatile("cp.async.commit_group;\n" ::: "memory");
                asm volatile("cp.async.wait_group 1;\n" ::: "memory");
            } else {
                asm volatile("cp.async.wait_group 0;\n" ::: "memory");
            }
            __syncwarp();

            const float* hb = myb + (s & 1) * (SUBK * BATCH);
            const ull*   wb = wk2 + (kb2 + s * 8) * 8 + c0;
#pragma unroll
            for (int kl2 = 0; kl2 < 8; ++kl2) {
                const float* g = hb + kl2 * 128;          // 32 granules * 4 floats
                ulonglong2 hA = *(const ulonglong2*)(g + jp * 4);          // rows 2jp,2jp+1 k-pairs
                ulonglong2 hB = *(const ulonglong2*)(g + (jp + 16) * 4);   // rows +32
                ulonglong2 wA = *(const ulonglong2*)(wb + kl2 * 8);        // cols c0,c0+1
                ulonglong2 wB = *(const ulonglong2*)(wb + kl2 * 8 + 2);    // cols c0+2,c0+3
                fma2(acc[0][0], hA.x, wA.x); fma2(acc[0][1], hA.x, wA.y);
                fma2(acc[0][2], hA.x, wB.x); fma2(acc[0][3], hA.x, wB.y);
                fma2(acc[1][0], hA.y, wA.x); fma2(acc[1][1], hA.y, wA.y);
                fma2(acc[1][2], hA.y, wB.x); fma2(acc[1][3], hA.y, wB.y);
                fma2(acc[2][0], hB.x, wA.x); fma2(acc[2][1], hB.x, wA.y);
                fma2(acc[2][2], hB.x, wB.x); fma2(acc[2][3], hB.x, wB.y);
                fma2(acc[3][0], hB.y, wA.x); fma2(acc[3][1], hB.y, wA.y);
                fma2(acc[3][2], hB.y, wB.x); fma2(acc[3][3], hB.y, wB.y);
            }
            __syncwarp();   // all lanes done reading before buffer is re-staged
        }

        // fold even/odd k partials, pack row-pairs, store partials
        float f[4][4];
#pragma unroll
        for (int i = 0; i < 4; ++i)
#pragma unroll
            for (int j = 0; j < 4; ++j) {
                float a, b;
                unpack2(acc[i][j], a, b);
                f[i][j] = a + b;
            }
#pragma unroll
        for (int j = 0; j < 4; ++j)
#pragma unroll
            for (int half = 0; half < 2; ++half) {
                int o = (c0 + j) * 32 + half * 16 + jp;
                red[o * RED_PITCH + wid] =
                    pack2(f[half * 2 + 0][j], f[half * 2 + 1][j]);
            }
        __syncthreads();

        // distributed epilogue: 256 threads, one row-pair output each
        if (tid < 256) {
            ull a = 0ULL;
#pragma unroll
            for (int w = 0; w < NWARPS; ++w)
                a = add2(a, red[oE * RED_PITCH + w]);

            float v0, v1;
            unpack2(a, v0, v1);
            v0 = tanhf(v0 + xp0);
            v1 = tanhf(v1 + xp1);

            // hidden state to output history
            outt[eo0] = v0;
            outt[eo1] = v1;

            // granule-layout copy for next step's staging (2 scalar stores:
            // rows row0E, row0E+1 sit at granule pos (c&1) and 2+(c&1))
            ghn[ghn_base]     = v0;
            ghn[ghn_base + 2] = v1;

            // prefetch next step's xp; latency hides under the grid barrier
            if (t + 1 < T_STEPS) {
                const float* outn = outt + BATCH * H_DIM;
                xp0 = outn[eo0];
                xp1 = outn[eo1];
            }
        }

        grid_barrier();
    }
}

// ---------------------------------------------------------------------------
extern "C" void kernel_launch(void* const* d_in, const int* in_sizes, int n_in,
                              void* d_out, int out_size)
{
    (void)in_sizes; (void)n_in; (void)out_size;
    const float* x = (const float*)d_in[0];
    const float* h = (const float*)d_in[1];
    const float* W = (const float*)d_in[2];
    const float* b = (const float*)d_in[3];
    float* out = (float*)d_out;

    // 1) xproj = x @ Wx + b  -> out
    dim3 grid_x(H_DIM / 64, (T_STEPS * BATCH) / 64);
    xproj_kernel<<<grid_x, 256>>>(x, W, b, out);

    // 2) persistent recurrent scan
    // smem: weights 32768 + warp buffers 131072 + reduction 34816 = 198656 B
    const size_t smem_bytes = 32768
                            + (size_t)NWARPS * 2 * SUBK * BATCH * sizeof(float)
                            + 256 * RED_PITCH * sizeof(ull);
    static int smem_set = 0;
    if (!smem_set) {
        cudaFuncSetAttribute(scan_kernel, cudaFuncAttributeMaxDynamicSharedMemorySize,
                             (int)smem_bytes);
        smem_set = 1;
    }
    scan_kernel<<<NCTA, SCAN_THREADS, smem_bytes>>>(h, W, out);
}